// round 14
// baseline (speedup 1.0000x reference)
#include <cuda_runtime.h>
#include <cuda_fp16.h>
#include <math.h>
#include <stdint.h>

#define Bsz 2
#define Tsz 2048
#define Csz 1024
#define Hn  16
#define HDd 64

#define SCALE_L2E 0.1803368801111244f   // 0.125 * log2(e)

// Scratch (fp16 pipeline)
__device__ __half g_xh [Bsz * Tsz * Csz];
__device__ __half g_wah[Csz * 3 * Csz];
__device__ __half g_wph[Csz * Csz];
__device__ __half g_qh[Bsz * Hn * Tsz * HDd];   // pre-scaled by SCALE_L2E
__device__ __half g_kh[Bsz * Hn * Tsz * HDd];
__device__ __half g_vh[Bsz * Hn * Tsz * HDd];
__device__ __half g_yh[Bsz * Tsz * Csz];

// ===========================================================================
// Helpers
// ===========================================================================
__device__ __forceinline__ uint32_t smem_u32(const void* p) {
    uint32_t a;
    asm("{ .reg .u64 t; cvta.to.shared.u64 t, %1; cvt.u32.u64 %0, t; }"
        : "=r"(a) : "l"(p));
    return a;
}

#define LDSM4(r0, r1, r2, r3, ad)                                              \
    asm volatile("ldmatrix.sync.aligned.m8n8.x4.shared.b16 {%0,%1,%2,%3}, [%4];" \
                 : "=r"(r0), "=r"(r1), "=r"(r2), "=r"(r3) : "r"(ad))

#define LDSM4T(r0, r1, r2, r3, ad)                                             \
    asm volatile("ldmatrix.sync.aligned.m8n8.x4.trans.shared.b16 {%0,%1,%2,%3}, [%4];" \
                 : "=r"(r0), "=r"(r1), "=r"(r2), "=r"(r3) : "r"(ad))

#define MMA16816(d, a, b0, b1)                                                 \
    asm volatile("mma.sync.aligned.m16n8k16.row.col.f32.f16.f16.f32 "          \
                 "{%0,%1,%2,%3}, {%4,%5,%6,%7}, {%8,%9}, {%0,%1,%2,%3};"       \
                 : "+f"((d)[0]), "+f"((d)[1]), "+f"((d)[2]), "+f"((d)[3])      \
                 : "r"((a)[0]), "r"((a)[1]), "r"((a)[2]), "r"((a)[3]),         \
                   "r"(b0), "r"(b1))

#define CP_ASYNC16(dst, src)                                                   \
    asm volatile("cp.async.cg.shared.global [%0], [%1], 16;"                   \
                 :: "r"(dst), "l"(src))
#define CP_COMMIT() asm volatile("cp.async.commit_group;" ::: "memory")
#define CP_WAIT1()  asm volatile("cp.async.wait_group 1;" ::: "memory")
#define CP_WAIT0()  asm volatile("cp.async.wait_group 0;" ::: "memory")

__device__ __forceinline__ float ex2f(float x) {
    float y;
    asm("ex2.approx.f32 %0, %1;" : "=f"(y) : "f"(x));
    return y;
}
__device__ __forceinline__ uint32_t packh2(float hi, float lo) {
    uint32_t r;
    asm("cvt.rn.f16x2.f32 %0, %1, %2;" : "=r"(r) : "f"(hi), "f"(lo));
    return r;
}
__device__ __forceinline__ uint32_t hex2(uint32_t x) {
    uint32_t y;
    asm("ex2.approx.f16x2 %0, %1;" : "=r"(y) : "r"(x));
    return y;
}

// ===========================================================================
// fp32 -> fp16 convert: three arrays in one launch
// ===========================================================================
__global__ void f2h3_kernel(const float* __restrict__ a, __half* __restrict__ ah, int na4,
                            const float* __restrict__ b, __half* __restrict__ bh, int nb4,
                            const float* __restrict__ c, __half* __restrict__ ch, int nc4) {
    int i = blockIdx.x * blockDim.x + threadIdx.x;
    const float* src; __half* dst;
    if (i < na4) { src = a; dst = ah; }
    else if (i < na4 + nb4) { i -= na4; src = b; dst = bh; }
    else { i -= na4 + nb4; if (i >= nc4) return; src = c; dst = ch; }
    float4 v = ((const float4*)src)[i];
    ((__half2*)dst)[2 * i]     = __floats2half2_rn(v.x, v.y);
    ((__half2*)dst)[2 * i + 1] = __floats2half2_rn(v.z, v.w);
}

// ===========================================================================
// HGEMM: 128x128 tile, BK=32, 8 warps (2M x 4N), warp tile 64x32, m16n8k16.
// 3-stage cp.async pipeline, ONE barrier per iteration.
// MODE 0: C = A@B + bias, fp32 out (proj).
// MODE 1: fused QKV epilogue — bias + RoPE + head-split/transpose, fp16 out.
// ===========================================================================
#define GSTAGE 24576
#define HG_SMEM (3 * GSTAGE)

template <int MODE>
__global__ __launch_bounds__(256, 2)
void hgemm128(const __half* __restrict__ A, const __half* __restrict__ B,
              const float* __restrict__ bias, float* __restrict__ Cv,
              int M, int N, int K) {
    extern __shared__ char sm[];
    const uint32_t sbase = smem_u32(sm);

    const int tid  = threadIdx.x;
    const int lane = tid & 31;
    const int wid  = tid >> 5;
    const int wm = wid >> 2;
    const int wn = wid & 3;
    const int m0 = blockIdx.y * 128;
    const int n0 = blockIdx.x * 128;
    const int NK = K >> 5;

    float acc[4][4][4] = {};

    auto issue = [&](int stg, int k0) {
        const uint32_t sA = sbase + stg * GSTAGE;
        const uint32_t sB = sA + 16384;
        #pragma unroll
        for (int i = 0; i < 2; i++) {
            const int idx = tid + i * 256;
            const int ra = idx >> 2, ca = idx & 3;
            CP_ASYNC16(sA + ra * 128 + ((ca ^ (ra & 7)) << 4),
                       A + (size_t)(m0 + ra) * K + k0 + ca * 8);
            const int rb = idx >> 4, cb = idx & 15;
            CP_ASYNC16(sB + rb * 256 + ((cb ^ (rb & 7)) << 4),
                       B + (size_t)(k0 + rb) * N + n0 + cb * 8);
        }
        CP_COMMIT();
    };

    issue(0, 0);
    issue(1, 32);

    for (int it = 0; it < NK; it++) {
        if (it == NK - 1) { CP_WAIT0(); } else { CP_WAIT1(); }
        __syncthreads();
        if (it + 2 < NK) issue((it + 2) % 3, (it + 2) * 32);

        const int stg = it % 3;
        const uint32_t aB = sbase + stg * GSTAGE;
        const uint32_t bB = aB + 16384;

        uint32_t vb[4][4];
        #pragma unroll
        for (int j = 0; j < 4; j++) {
            const int cn = wn * 4 + j;
            LDSM4T(vb[j][0], vb[j][1], vb[j][2], vb[j][3],
                   bB + lane * 256 + ((cn ^ (lane & 7)) << 4));
        }
        #pragma unroll
        for (int ks = 0; ks < 2; ks++) {
            uint32_t af[4][4];
            #pragma unroll
            for (int mt = 0; mt < 4; mt++) {
                const int row = wm * 64 + mt * 16 + (lane & 7) + ((lane >> 3) & 1) * 8;
                const int ch  = ks * 2 + (lane >> 4);
                LDSM4(af[mt][0], af[mt][1], af[mt][2], af[mt][3],
                      aB + row * 128 + ((ch ^ (row & 7)) << 4));
            }
            #pragma unroll
            for (int mt = 0; mt < 4; mt++)
                #pragma unroll
                for (int j = 0; j < 4; j++)
                    MMA16816(acc[mt][j], af[mt], vb[j][2 * ks], vb[j][2 * ks + 1]);
        }
    }

    if (MODE == 0) {
        #pragma unroll
        for (int mt = 0; mt < 4; mt++) {
            const int row_lo = m0 + wm * 64 + mt * 16 + (lane >> 2);
            const int row_hi = row_lo + 8;
            #pragma unroll
            for (int j = 0; j < 4; j++) {
                const int col = n0 + wn * 32 + j * 8 + (lane & 3) * 2;
                const float b0v = bias[col], b1v = bias[col + 1];
                float2 o0 = {acc[mt][j][0] + b0v, acc[mt][j][1] + b1v};
                float2 o1 = {acc[mt][j][2] + b0v, acc[mt][j][3] + b1v};
                *(float2*)&Cv[(size_t)row_lo * N + col] = o0;
                *(float2*)&Cv[(size_t)row_hi * N + col] = o1;
            }
        }
    } else {
        float* Cs = (float*)sm;   // 128 x 132 floats
        __syncthreads();
        #pragma unroll
        for (int mt = 0; mt < 4; mt++) {
            const int rl = wm * 64 + mt * 16 + (lane >> 2);
            #pragma unroll
            for (int j = 0; j < 4; j++) {
                const int cl = wn * 32 + j * 8 + (lane & 3) * 2;
                const float b0v = bias[n0 + cl], b1v = bias[n0 + cl + 1];
                Cs[rl * 132 + cl]           = acc[mt][j][0] + b0v;
                Cs[rl * 132 + cl + 1]       = acc[mt][j][1] + b1v;
                Cs[(rl + 8) * 132 + cl]     = acc[mt][j][2] + b0v;
                Cs[(rl + 8) * 132 + cl + 1] = acc[mt][j][3] + b1v;
            }
        }
        __syncthreads();

        const int region = n0 >> 10;
        const int hbase  = (n0 & 1023) >> 6;
        #pragma unroll 4
        for (int i = 0; i < 16; i++) {
            const int p  = tid + (i << 8);
            const int r  = p >> 5;
            const int d2 = p & 31;
            const int mrow = m0 + r;
            const int tpos = mrow & (Tsz - 1);
            const int bidx = mrow >> 11;
            float sn = 0.0f, cs = 0.0f;
            if (region < 2) {
                const float inv_ts =
                    exp2f(-(float)d2 * (13.287712379549449f / 32.0f));
                sincosf((float)tpos * inv_ts, &sn, &cs);
            }
            #pragma unroll
            for (int hh = 0; hh < 2; hh++) {
                const float first  = Cs[r * 132 + hh * 64 + d2];
                const float second = Cs[r * 132 + hh * 64 + d2 + 32];
                const size_t o =
                    ((size_t)(bidx * Hn + hbase + hh) * Tsz + tpos) * 64 + d2;
                if (region == 0) {
                    g_qh[o]      = __float2half_rn((first * cs - second * sn) * SCALE_L2E);
                    g_qh[o + 32] = __float2half_rn((second * cs + first * sn) * SCALE_L2E);
                } else if (region == 1) {
                    g_kh[o]      = __float2half_rn(first * cs - second * sn);
                    g_kh[o + 32] = __float2half_rn(second * cs + first * sn);
                } else {
                    g_vh[o]      = __float2half_rn(first);
                    g_vh[o + 32] = __float2half_rn(second);
                }
            }
        }
    }
}

// ===========================================================================
// Flash attention via mma.sync (fp16 in, fp32 accum), fp16 out.
// 128 threads / 4 warps; Q tile 64 (16 rows/warp), KV tile 128.
// Software-pipelined: GEMM1 of tile kt+1 issued before softmax/GEMM2 of kt
// (independent HMMA work overlaps the MUFU/ALU softmax phase).
// l-sum reduction deferred to the epilogue (per-thread partials).
// Smem 104KB -> 2 CTAs/SM; __launch_bounds__(128,2) caps regs at 256.
// ===========================================================================
#define FL_SMEM 106496

__global__ __launch_bounds__(128, 2)
void flash_mma(const __half* __restrict__ Q,
               const __half* __restrict__ K,
               const __half* __restrict__ V,
               __half* __restrict__ Y) {
    extern __shared__ char smem[];
    char* Qs = smem;                      // 8 KB
    char* Kbase = smem + 8192;            // 3 x 16 KB
    char* Vbase = smem + 57344;           // 3 x 16 KB

    const int tid  = threadIdx.x;
    const int wid  = tid >> 5;
    const int lane = tid & 31;
    const int g = lane >> 2;
    const int t = lane & 3;

    const int qt = gridDim.x - 1 - blockIdx.x;
    const int h  = blockIdx.y;
    const int b  = blockIdx.z;
    const size_t bh = (size_t)(b * Hn + h) * Tsz;
    const int qbase = qt * 64 + wid * 16;
    const int row_lo = qbase + g;
    const int row_hi = row_lo + 8;
    const int nkt = (qt >> 1) + 1;

    auto fl_issue = [&](int tile) {
        const uint32_t kB = smem_u32(Kbase + (tile % 3) * 16384);
        const uint32_t vB = smem_u32(Vbase + (tile % 3) * 16384);
        const size_t base = bh + (size_t)tile * 128;
        #pragma unroll
        for (int i = 0; i < 8; i++) {
            const int idx = tid + i * 128;
            const int r = idx >> 3;
            const int c = idx & 7;
            const uint32_t so = r * 128 + ((c ^ (r & 7)) << 4);
            CP_ASYNC16(kB + so, &K[(base + r) * HDd + c * 8]);
            CP_ASYNC16(vB + so, &V[(base + r) * HDd + c * 8]);
        }
        CP_COMMIT();
    };

    // Q tile: swizzled copy
    #pragma unroll
    for (int i = 0; i < 4; i++) {
        const int idx = tid + i * 128;
        const int r = idx >> 3;
        const int c = idx & 7;
        uint4 q = *(const uint4*)&Q[(bh + qt * 64 + r) * HDd + c * 8];
        *(uint4*)(Qs + r * 128 + ((c ^ (r & 7)) << 4)) = q;
    }
    fl_issue(0);
    if (nkt > 1) { fl_issue(1); CP_WAIT1(); } else { CP_WAIT0(); }
    __syncthreads();   // Q visible + tile 0 visible

    // Q fragments (persistent)
    uint32_t qf[4][4];
    {
        const uint32_t sQ = smem_u32(Qs);
        const int mat = lane >> 3;
        const int qr  = wid * 16 + (lane & 7) + ((mat & 1) << 3);
        #pragma unroll
        for (int k = 0; k < 4; k++) {
            const int chunk = 2 * k + (mat >> 1);
            LDSM4(qf[k][0], qf[k][1], qf[k][2], qf[k][3],
                  sQ + qr * 128 + (((chunk ^ (qr & 7))) << 4));
        }
    }

    float oacc[8][4] = {};
    float mst[2] = {-1e30f, -1e30f};
    float lst[2] = {0.0f, 0.0f};   // per-thread partials; reduced at the end

    // GEMM1: S = Q @ K^T for buffer bufIdx
    auto gemm1 = [&](float (&s)[16][4], int bufIdx) {
        const uint32_t sK = smem_u32(Kbase + bufIdx * 16384);
        const int kr = lane & 7;
        const int c0 = lane >> 3;
        #pragma unroll
        for (int n = 0; n < 16; n++) {
            s[n][0] = s[n][1] = s[n][2] = s[n][3] = 0.0f;
            const int row = n * 8 + kr;
            uint32_t kb[8];
            const uint32_t rb = sK + row * 128;
            LDSM4(kb[0], kb[1], kb[2], kb[3],
                  rb + (((c0 ^ (row & 7))) << 4));
            LDSM4(kb[4], kb[5], kb[6], kb[7],
                  rb + ((((c0 + 4) ^ (row & 7))) << 4));
            #pragma unroll
            for (int k = 0; k < 4; k++)
                MMA16816(s[n], qf[k], kb[2 * k], kb[2 * k + 1]);
        }
    };

    // softmax + GEMM2 for tile kt using scores s
    auto soft_pv = [&](float (&s)[16][4], int kt) {
        const bool dotest = (kt == nkt - 1);
        float rmx_lo = -1e30f, rmx_hi = -1e30f;
        #pragma unroll
        for (int n = 0; n < 16; n++) {
            if (dotest) {
                const int cb = kt * 128 + n * 8 + 2 * t;
                if (cb     > row_lo) s[n][0] = -1e30f;
                if (cb + 1 > row_lo) s[n][1] = -1e30f;
                if (cb     > row_hi) s[n][2] = -1e30f;
                if (cb + 1 > row_hi) s[n][3] = -1e30f;
            }
            rmx_lo = fmaxf(rmx_lo, fmaxf(s[n][0], s[n][1]));
            rmx_hi = fmaxf(rmx_hi, fmaxf(s[n][2], s[n][3]));
        }
        rmx_lo = fmaxf(rmx_lo, __shfl_xor_sync(0xffffffffu, rmx_lo, 1));
        rmx_lo = fmaxf(rmx_lo, __shfl_xor_sync(0xffffffffu, rmx_lo, 2));
        rmx_hi = fmaxf(rmx_hi, __shfl_xor_sync(0xffffffffu, rmx_hi, 1));
        rmx_hi = fmaxf(rmx_hi, __shfl_xor_sync(0xffffffffu, rmx_hi, 2));

        const float mn_lo = fmaxf(mst[0], rmx_lo);
        const float mn_hi = fmaxf(mst[1], rmx_hi);
        const float corr_lo = ex2f(mst[0] - mn_lo);
        const float corr_hi = ex2f(mst[1] - mn_hi);
        mst[0] = mn_lo; mst[1] = mn_hi;

        uint32_t ph_lo[16], ph_hi[16];
        float sum_lo = 0.0f, sum_hi = 0.0f;
        #pragma unroll
        for (int n = 0; n < 16; n++) {
            ph_lo[n] = hex2(packh2(s[n][1] - mn_lo, s[n][0] - mn_lo));
            ph_hi[n] = hex2(packh2(s[n][3] - mn_hi, s[n][2] - mn_hi));
            const float2 flo = __half22float2(*(__half2*)&ph_lo[n]);
            const float2 fhi = __half22float2(*(__half2*)&ph_hi[n]);
            sum_lo += flo.x + flo.y;
            sum_hi += fhi.x + fhi.y;
        }
        lst[0] = lst[0] * corr_lo + sum_lo;    // per-thread partial (no shuffles)
        lst[1] = lst[1] * corr_hi + sum_hi;

        #pragma unroll
        for (int n = 0; n < 8; n++) {
            oacc[n][0] *= corr_lo; oacc[n][1] *= corr_lo;
            oacc[n][2] *= corr_hi; oacc[n][3] *= corr_hi;
        }

        const uint32_t sV = smem_u32(Vbase + (kt % 3) * 16384);
        #pragma unroll
        for (int kh = 0; kh < 2; kh++) {
            uint32_t pf[4][4];
            #pragma unroll
            for (int k = 0; k < 4; k++) {
                const int s0 = 8 * kh + 2 * k;
                pf[k][0] = ph_lo[s0];
                pf[k][1] = ph_hi[s0];
                pf[k][2] = ph_lo[s0 + 1];
                pf[k][3] = ph_hi[s0 + 1];
            }
            const int vr  = kh * 64 + (lane >> 3) * 8 + (lane & 7);
            const int vr2 = vr + 32;
            #pragma unroll
            for (int n = 0; n < 8; n++) {
                uint32_t vb[8];
                LDSM4T(vb[0], vb[1], vb[2], vb[3],
                       sV + vr * 128 + (((n ^ (vr & 7))) << 4));
                LDSM4T(vb[4], vb[5], vb[6], vb[7],
                       sV + vr2 * 128 + (((n ^ (vr2 & 7))) << 4));
                #pragma unroll
                for (int k = 0; k < 4; k++)
                    MMA16816(oacc[n], pf[k], vb[2 * k], vb[2 * k + 1]);
            }
        }
    };

    float sA[16][4], sB[16][4];
    gemm1(sA, 0);   // tile 0 scores

    // pipelined body: consumes sCur (= tile kt), precomputes sNxt (= tile kt+1)
    auto body = [&](float (&sCur)[16][4], float (&sNxt)[16][4], int kt) {
        if (kt >= nkt) return;
        const bool haveNext = (kt + 1 < nkt);
        if (haveNext) {
            CP_WAIT0();        // tiles <= kt+1 complete
            __syncthreads();   // visibility + buffer-reuse ordering
            if (kt + 2 < nkt) fl_issue(kt + 2);
            gemm1(sNxt, (kt + 1) % 3);   // independent HMMA ahead of softmax
        }
        soft_pv(sCur, kt);
    };

    for (int kt = 0; kt < nkt; kt += 2) {
        body(sA, sB, kt);
        body(sB, sA, kt + 1);
    }

    // Epilogue: quad-reduce l partials, normalize, store fp16
    lst[0] += __shfl_xor_sync(0xffffffffu, lst[0], 1);
    lst[0] += __shfl_xor_sync(0xffffffffu, lst[0], 2);
    lst[1] += __shfl_xor_sync(0xffffffffu, lst[1], 1);
    lst[1] += __shfl_xor_sync(0xffffffffu, lst[1], 2);
    const float inv_lo = 1.0f / lst[0];
    const float inv_hi = 1.0f / lst[1];
    #pragma unroll
    for (int n = 0; n < 8; n++) {
        const int col = h * HDd + n * 8 + 2 * t;
        *(__half2*)&Y[((size_t)(b * Tsz) + row_lo) * Csz + col] =
            __floats2half2_rn(oacc[n][0] * inv_lo, oacc[n][1] * inv_lo);
        *(__half2*)&Y[((size_t)(b * Tsz) + row_hi) * Csz + col] =
            __floats2half2_rn(oacc[n][2] * inv_hi, oacc[n][3] * inv_hi);
    }
}

// ===========================================================================
extern "C" void kernel_launch(void* const* d_in, const int* in_sizes, int n_in,
                              void* d_out, int out_size) {
    (void)in_sizes; (void)n_in; (void)out_size;
    const float* x      = (const float*)d_in[0];
    const float* w_attn = (const float*)d_in[1];
    const float* b_attn = (const float*)d_in[2];
    const float* w_proj = (const float*)d_in[3];
    const float* b_proj = (const float*)d_in[4];
    float* out = (float*)d_out;

    __half *p_xh, *p_wah, *p_wph, *p_qh, *p_kh, *p_vh, *p_yh;
    cudaGetSymbolAddress((void**)&p_xh,  g_xh);
    cudaGetSymbolAddress((void**)&p_wah, g_wah);
    cudaGetSymbolAddress((void**)&p_wph, g_wph);
    cudaGetSymbolAddress((void**)&p_qh,  g_qh);
    cudaGetSymbolAddress((void**)&p_kh,  g_kh);
    cudaGetSymbolAddress((void**)&p_vh,  g_vh);
    cudaGetSymbolAddress((void**)&p_yh,  g_yh);

    const int M = Bsz * Tsz;  // 4096
    const int na4 = M * Csz / 4;
    const int nb4 = Csz * 3 * Csz / 4;
    const int nc4 = Csz * Csz / 4;

    // 0) fp32 -> fp16 converts (single launch)
    f2h3_kernel<<<(na4 + nb4 + nc4 + 255) / 256, 256>>>(
        x, p_xh, na4, w_attn, p_wah, nb4, w_proj, p_wph, nc4);

    // 1) QKV GEMM with fused bias + RoPE + split/transpose epilogue
    cudaFuncSetAttribute(hgemm128<1>,
                         cudaFuncAttributeMaxDynamicSharedMemorySize, HG_SMEM);
    hgemm128<1><<<dim3(3 * Csz / 128, M / 128), 256, HG_SMEM>>>(
        p_xh, p_wah, b_attn, nullptr, M, 3 * Csz, Csz);

    // 2) Flash attention (fp16 out; Q tile 64, 2 CTAs/SM, pipelined)
    cudaFuncSetAttribute(flash_mma,
                         cudaFuncAttributeMaxDynamicSharedMemorySize, FL_SMEM);
    flash_mma<<<dim3(Tsz / 64, Hn, Bsz), 128, FL_SMEM>>>(p_qh, p_kh, p_vh, p_yh);

    // 3) out = y @ w_proj + b_proj   (fp32 out)
    cudaFuncSetAttribute(hgemm128<0>,
                         cudaFuncAttributeMaxDynamicSharedMemorySize, HG_SMEM);
    hgemm128<0><<<dim3(Csz / 128, M / 128), 256, HG_SMEM>>>(
        p_yh, p_wph, b_proj, out, M, Csz, Csz);
}

// round 15
// speedup vs baseline: 1.0650x; 1.0650x over previous
#include <cuda_runtime.h>
#include <cuda_fp16.h>
#include <math.h>
#include <stdint.h>

#define Bsz 2
#define Tsz 2048
#define Csz 1024
#define Hn  16
#define HDd 64

#define SCALE_L2E 0.1803368801111244f   // 0.125 * log2(e)

// Scratch (fp16 pipeline)
__device__ __half g_xh [Bsz * Tsz * Csz];
__device__ __half g_wah[Csz * 3 * Csz];
__device__ __half g_wph[Csz * Csz];
__device__ __half g_qh[Bsz * Hn * Tsz * HDd];   // pre-scaled by SCALE_L2E
__device__ __half g_kh[Bsz * Hn * Tsz * HDd];
__device__ __half g_vh[Bsz * Hn * Tsz * HDd];
__device__ __half g_yh[Bsz * Tsz * Csz];

// ===========================================================================
// Helpers
// ===========================================================================
__device__ __forceinline__ uint32_t smem_u32(const void* p) {
    uint32_t a;
    asm("{ .reg .u64 t; cvta.to.shared.u64 t, %1; cvt.u32.u64 %0, t; }"
        : "=r"(a) : "l"(p));
    return a;
}

#define LDSM4(r0, r1, r2, r3, ad)                                              \
    asm volatile("ldmatrix.sync.aligned.m8n8.x4.shared.b16 {%0,%1,%2,%3}, [%4];" \
                 : "=r"(r0), "=r"(r1), "=r"(r2), "=r"(r3) : "r"(ad))

#define LDSM4T(r0, r1, r2, r3, ad)                                             \
    asm volatile("ldmatrix.sync.aligned.m8n8.x4.trans.shared.b16 {%0,%1,%2,%3}, [%4];" \
                 : "=r"(r0), "=r"(r1), "=r"(r2), "=r"(r3) : "r"(ad))

#define MMA16816(d, a, b0, b1)                                                 \
    asm volatile("mma.sync.aligned.m16n8k16.row.col.f32.f16.f16.f32 "          \
                 "{%0,%1,%2,%3}, {%4,%5,%6,%7}, {%8,%9}, {%0,%1,%2,%3};"       \
                 : "+f"((d)[0]), "+f"((d)[1]), "+f"((d)[2]), "+f"((d)[3])      \
                 : "r"((a)[0]), "r"((a)[1]), "r"((a)[2]), "r"((a)[3]),         \
                   "r"(b0), "r"(b1))

#define CP_ASYNC16(dst, src)                                                   \
    asm volatile("cp.async.cg.shared.global [%0], [%1], 16;"                   \
                 :: "r"(dst), "l"(src))
#define CP_COMMIT() asm volatile("cp.async.commit_group;" ::: "memory")
#define CP_WAIT1()  asm volatile("cp.async.wait_group 1;" ::: "memory")
#define CP_WAIT0()  asm volatile("cp.async.wait_group 0;" ::: "memory")

__device__ __forceinline__ float ex2f(float x) {
    float y;
    asm("ex2.approx.f32 %0, %1;" : "=f"(y) : "f"(x));
    return y;
}
__device__ __forceinline__ uint32_t packh2(float hi, float lo) {
    uint32_t r;
    asm("cvt.rn.f16x2.f32 %0, %1, %2;" : "=r"(r) : "f"(hi), "f"(lo));
    return r;
}
__device__ __forceinline__ uint32_t hex2(uint32_t x) {
    uint32_t y;
    asm("ex2.approx.f16x2 %0, %1;" : "=r"(y) : "r"(x));
    return y;
}

// ===========================================================================
// fp32 -> fp16 convert: three arrays in one launch
// ===========================================================================
__global__ void f2h3_kernel(const float* __restrict__ a, __half* __restrict__ ah, int na4,
                            const float* __restrict__ b, __half* __restrict__ bh, int nb4,
                            const float* __restrict__ c, __half* __restrict__ ch, int nc4) {
    int i = blockIdx.x * blockDim.x + threadIdx.x;
    const float* src; __half* dst;
    if (i < na4) { src = a; dst = ah; }
    else if (i < na4 + nb4) { i -= na4; src = b; dst = bh; }
    else { i -= na4 + nb4; if (i >= nc4) return; src = c; dst = ch; }
    float4 v = ((const float4*)src)[i];
    ((__half2*)dst)[2 * i]     = __floats2half2_rn(v.x, v.y);
    ((__half2*)dst)[2 * i + 1] = __floats2half2_rn(v.z, v.w);
}

// ===========================================================================
// HGEMM: 128x128 tile, BK=32, 8 warps (2M x 4N), warp tile 64x32, m16n8k16.
// 3-stage cp.async pipeline, ONE barrier per iteration.
// MODE 0: C = A@B + bias, fp32 out (proj).
// MODE 1: fused QKV epilogue — bias + RoPE + head-split/transpose, fp16 out.
// ===========================================================================
#define GSTAGE 24576
#define HG_SMEM (3 * GSTAGE)

template <int MODE>
__global__ __launch_bounds__(256, 2)
void hgemm128(const __half* __restrict__ A, const __half* __restrict__ B,
              const float* __restrict__ bias, float* __restrict__ Cv,
              int M, int N, int K) {
    extern __shared__ char sm[];
    const uint32_t sbase = smem_u32(sm);

    const int tid  = threadIdx.x;
    const int lane = tid & 31;
    const int wid  = tid >> 5;
    const int wm = wid >> 2;
    const int wn = wid & 3;
    const int m0 = blockIdx.y * 128;
    const int n0 = blockIdx.x * 128;
    const int NK = K >> 5;

    float acc[4][4][4] = {};

    auto issue = [&](int stg, int k0) {
        const uint32_t sA = sbase + stg * GSTAGE;
        const uint32_t sB = sA + 16384;
        #pragma unroll
        for (int i = 0; i < 2; i++) {
            const int idx = tid + i * 256;
            const int ra = idx >> 2, ca = idx & 3;
            CP_ASYNC16(sA + ra * 128 + ((ca ^ (ra & 7)) << 4),
                       A + (size_t)(m0 + ra) * K + k0 + ca * 8);
            const int rb = idx >> 4, cb = idx & 15;
            CP_ASYNC16(sB + rb * 256 + ((cb ^ (rb & 7)) << 4),
                       B + (size_t)(k0 + rb) * N + n0 + cb * 8);
        }
        CP_COMMIT();
    };

    issue(0, 0);
    issue(1, 32);

    for (int it = 0; it < NK; it++) {
        if (it == NK - 1) { CP_WAIT0(); } else { CP_WAIT1(); }
        __syncthreads();
        if (it + 2 < NK) issue((it + 2) % 3, (it + 2) * 32);

        const int stg = it % 3;
        const uint32_t aB = sbase + stg * GSTAGE;
        const uint32_t bB = aB + 16384;

        uint32_t vb[4][4];
        #pragma unroll
        for (int j = 0; j < 4; j++) {
            const int cn = wn * 4 + j;
            LDSM4T(vb[j][0], vb[j][1], vb[j][2], vb[j][3],
                   bB + lane * 256 + ((cn ^ (lane & 7)) << 4));
        }
        #pragma unroll
        for (int ks = 0; ks < 2; ks++) {
            uint32_t af[4][4];
            #pragma unroll
            for (int mt = 0; mt < 4; mt++) {
                const int row = wm * 64 + mt * 16 + (lane & 7) + ((lane >> 3) & 1) * 8;
                const int ch  = ks * 2 + (lane >> 4);
                LDSM4(af[mt][0], af[mt][1], af[mt][2], af[mt][3],
                      aB + row * 128 + ((ch ^ (row & 7)) << 4));
            }
            #pragma unroll
            for (int mt = 0; mt < 4; mt++)
                #pragma unroll
                for (int j = 0; j < 4; j++)
                    MMA16816(acc[mt][j], af[mt], vb[j][2 * ks], vb[j][2 * ks + 1]);
        }
    }

    if (MODE == 0) {
        #pragma unroll
        for (int mt = 0; mt < 4; mt++) {
            const int row_lo = m0 + wm * 64 + mt * 16 + (lane >> 2);
            const int row_hi = row_lo + 8;
            #pragma unroll
            for (int j = 0; j < 4; j++) {
                const int col = n0 + wn * 32 + j * 8 + (lane & 3) * 2;
                const float b0v = bias[col], b1v = bias[col + 1];
                float2 o0 = {acc[mt][j][0] + b0v, acc[mt][j][1] + b1v};
                float2 o1 = {acc[mt][j][2] + b0v, acc[mt][j][3] + b1v};
                *(float2*)&Cv[(size_t)row_lo * N + col] = o0;
                *(float2*)&Cv[(size_t)row_hi * N + col] = o1;
            }
        }
    } else {
        float* Cs = (float*)sm;   // 128 x 132 floats
        __syncthreads();
        #pragma unroll
        for (int mt = 0; mt < 4; mt++) {
            const int rl = wm * 64 + mt * 16 + (lane >> 2);
            #pragma unroll
            for (int j = 0; j < 4; j++) {
                const int cl = wn * 32 + j * 8 + (lane & 3) * 2;
                const float b0v = bias[n0 + cl], b1v = bias[n0 + cl + 1];
                Cs[rl * 132 + cl]           = acc[mt][j][0] + b0v;
                Cs[rl * 132 + cl + 1]       = acc[mt][j][1] + b1v;
                Cs[(rl + 8) * 132 + cl]     = acc[mt][j][2] + b0v;
                Cs[(rl + 8) * 132 + cl + 1] = acc[mt][j][3] + b1v;
            }
        }
        __syncthreads();

        const int region = n0 >> 10;
        const int hbase  = (n0 & 1023) >> 6;
        #pragma unroll 4
        for (int i = 0; i < 16; i++) {
            const int p  = tid + (i << 8);
            const int r  = p >> 5;
            const int d2 = p & 31;
            const int mrow = m0 + r;
            const int tpos = mrow & (Tsz - 1);
            const int bidx = mrow >> 11;
            float sn = 0.0f, cs = 0.0f;
            if (region < 2) {
                const float inv_ts =
                    exp2f(-(float)d2 * (13.287712379549449f / 32.0f));
                sincosf((float)tpos * inv_ts, &sn, &cs);
            }
            #pragma unroll
            for (int hh = 0; hh < 2; hh++) {
                const float first  = Cs[r * 132 + hh * 64 + d2];
                const float second = Cs[r * 132 + hh * 64 + d2 + 32];
                const size_t o =
                    ((size_t)(bidx * Hn + hbase + hh) * Tsz + tpos) * 64 + d2;
                if (region == 0) {
                    g_qh[o]      = __float2half_rn((first * cs - second * sn) * SCALE_L2E);
                    g_qh[o + 32] = __float2half_rn((second * cs + first * sn) * SCALE_L2E);
                } else if (region == 1) {
                    g_kh[o]      = __float2half_rn(first * cs - second * sn);
                    g_kh[o + 32] = __float2half_rn(second * cs + first * sn);
                } else {
                    g_vh[o]      = __float2half_rn(first);
                    g_vh[o + 32] = __float2half_rn(second);
                }
            }
        }
    }
}

// ===========================================================================
// Flash attention via mma.sync (fp16 in, fp32 accum), fp16 out.
// 128 threads / 4 warps; Q tile 64 (16 rows/warp), KV tile 128.
// R13 structure (single score buffer, CP_WAIT1 lookahead) + deferred l-sum.
// Smem: Q 8KB + K 3x16KB + V 3x16KB = 104KB -> 2 CTAs/SM.
// ===========================================================================
#define FL_SMEM 106496

__global__ __launch_bounds__(128)
void flash_mma(const __half* __restrict__ Q,
               const __half* __restrict__ K,
               const __half* __restrict__ V,
               __half* __restrict__ Y) {
    extern __shared__ char smem[];
    char* Qs = smem;                      // 8 KB
    char* Kbase = smem + 8192;            // 3 x 16 KB
    char* Vbase = smem + 57344;           // 3 x 16 KB

    const int tid  = threadIdx.x;
    const int wid  = tid >> 5;
    const int lane = tid & 31;
    const int g = lane >> 2;
    const int t = lane & 3;

    const int qt = gridDim.x - 1 - blockIdx.x;    // long blocks first
    const int h  = blockIdx.y;
    const int b  = blockIdx.z;
    const size_t bh = (size_t)(b * Hn + h) * Tsz;
    const int qbase = qt * 64 + wid * 16;
    const int row_lo = qbase + g;
    const int row_hi = row_lo + 8;
    const int nkt = (qt >> 1) + 1;

    auto fl_issue = [&](int tile) {
        const uint32_t kB = smem_u32(Kbase + (tile % 3) * 16384);
        const uint32_t vB = smem_u32(Vbase + (tile % 3) * 16384);
        const size_t base = bh + (size_t)tile * 128;
        #pragma unroll
        for (int i = 0; i < 8; i++) {
            const int idx = tid + i * 128;
            const int r = idx >> 3;
            const int c = idx & 7;
            const uint32_t so = r * 128 + ((c ^ (r & 7)) << 4);
            CP_ASYNC16(kB + so, &K[(base + r) * HDd + c * 8]);
            CP_ASYNC16(vB + so, &V[(base + r) * HDd + c * 8]);
        }
        CP_COMMIT();
    };

    // Q tile: swizzled copy
    #pragma unroll
    for (int i = 0; i < 4; i++) {
        const int idx = tid + i * 128;
        const int r = idx >> 3;
        const int c = idx & 7;
        uint4 q = *(const uint4*)&Q[(bh + qt * 64 + r) * HDd + c * 8];
        *(uint4*)(Qs + r * 128 + ((c ^ (r & 7)) << 4)) = q;
    }
    fl_issue(0);
    if (nkt > 1) fl_issue(1);

    __syncthreads();

    // Q fragments (persistent)
    uint32_t qf[4][4];
    {
        const uint32_t sQ = smem_u32(Qs);
        const int mat = lane >> 3;
        const int qr  = wid * 16 + (lane & 7) + ((mat & 1) << 3);
        #pragma unroll
        for (int k = 0; k < 4; k++) {
            const int chunk = 2 * k + (mat >> 1);
            LDSM4(qf[k][0], qf[k][1], qf[k][2], qf[k][3],
                  sQ + qr * 128 + (((chunk ^ (qr & 7))) << 4));
        }
    }

    float oacc[8][4] = {};
    float mst[2] = {-1e30f, -1e30f};
    float lst[2] = {0.0f, 0.0f};   // per-thread partials; reduced at the end

    for (int kt = 0; kt < nkt; kt++) {
        if (kt + 1 < nkt) { CP_WAIT1(); } else { CP_WAIT0(); }
        __syncthreads();
        if (kt + 2 < nkt) fl_issue(kt + 2);

        char* Kc = Kbase + (kt % 3) * 16384;
        char* Vc = Vbase + (kt % 3) * 16384;

        // GEMM1
        float sacc[16][4] = {};
        {
            const uint32_t sK = smem_u32(Kc);
            const int kr = lane & 7;
            const int c0 = lane >> 3;
            #pragma unroll
            for (int n = 0; n < 16; n++) {
                const int row = n * 8 + kr;
                uint32_t kb[8];
                const uint32_t rb = sK + row * 128;
                LDSM4(kb[0], kb[1], kb[2], kb[3],
                      rb + (((c0 ^ (row & 7))) << 4));
                LDSM4(kb[4], kb[5], kb[6], kb[7],
                      rb + ((((c0 + 4) ^ (row & 7))) << 4));
                #pragma unroll
                for (int k = 0; k < 4; k++)
                    MMA16816(sacc[n], qf[k], kb[2 * k], kb[2 * k + 1]);
            }
        }

        // Softmax (max still quad-reduced; l kept as per-thread partial)
        const bool dotest = (kt == nkt - 1);
        float rmx_lo = -1e30f, rmx_hi = -1e30f;
        #pragma unroll
        for (int n = 0; n < 16; n++) {
            if (dotest) {
                const int cb = kt * 128 + n * 8 + 2 * t;
                if (cb     > row_lo) sacc[n][0] = -1e30f;
                if (cb + 1 > row_lo) sacc[n][1] = -1e30f;
                if (cb     > row_hi) sacc[n][2] = -1e30f;
                if (cb + 1 > row_hi) sacc[n][3] = -1e30f;
            }
            rmx_lo = fmaxf(rmx_lo, fmaxf(sacc[n][0], sacc[n][1]));
            rmx_hi = fmaxf(rmx_hi, fmaxf(sacc[n][2], sacc[n][3]));
        }
        rmx_lo = fmaxf(rmx_lo, __shfl_xor_sync(0xffffffffu, rmx_lo, 1));
        rmx_lo = fmaxf(rmx_lo, __shfl_xor_sync(0xffffffffu, rmx_lo, 2));
        rmx_hi = fmaxf(rmx_hi, __shfl_xor_sync(0xffffffffu, rmx_hi, 1));
        rmx_hi = fmaxf(rmx_hi, __shfl_xor_sync(0xffffffffu, rmx_hi, 2));

        const float mn_lo = fmaxf(mst[0], rmx_lo);
        const float mn_hi = fmaxf(mst[1], rmx_hi);
        const float corr_lo = ex2f(mst[0] - mn_lo);
        const float corr_hi = ex2f(mst[1] - mn_hi);
        mst[0] = mn_lo; mst[1] = mn_hi;

        uint32_t ph_lo[16], ph_hi[16];
        float sum_lo = 0.0f, sum_hi = 0.0f;
        #pragma unroll
        for (int n = 0; n < 16; n++) {
            ph_lo[n] = hex2(packh2(sacc[n][1] - mn_lo, sacc[n][0] - mn_lo));
            ph_hi[n] = hex2(packh2(sacc[n][3] - mn_hi, sacc[n][2] - mn_hi));
            const float2 flo = __half22float2(*(__half2*)&ph_lo[n]);
            const float2 fhi = __half22float2(*(__half2*)&ph_hi[n]);
            sum_lo += flo.x + flo.y;
            sum_hi += fhi.x + fhi.y;
        }
        lst[0] = lst[0] * corr_lo + sum_lo;   // no shuffles here (deferred)
        lst[1] = lst[1] * corr_hi + sum_hi;

        #pragma unroll
        for (int n = 0; n < 8; n++) {
            oacc[n][0] *= corr_lo; oacc[n][1] *= corr_lo;
            oacc[n][2] *= corr_hi; oacc[n][3] *= corr_hi;
        }

        // GEMM2
        {
            const uint32_t sV = smem_u32(Vc);
            #pragma unroll
            for (int kh = 0; kh < 2; kh++) {
                uint32_t pf[4][4];
                #pragma unroll
                for (int k = 0; k < 4; k++) {
                    const int s0 = 8 * kh + 2 * k;
                    pf[k][0] = ph_lo[s0];
                    pf[k][1] = ph_hi[s0];
                    pf[k][2] = ph_lo[s0 + 1];
                    pf[k][3] = ph_hi[s0 + 1];
                }
                const int vr  = kh * 64 + (lane >> 3) * 8 + (lane & 7);
                const int vr2 = vr + 32;
                #pragma unroll
                for (int n = 0; n < 8; n++) {
                    uint32_t vb[8];
                    LDSM4T(vb[0], vb[1], vb[2], vb[3],
                           sV + vr * 128 + (((n ^ (vr & 7))) << 4));
                    LDSM4T(vb[4], vb[5], vb[6], vb[7],
                           sV + vr2 * 128 + (((n ^ (vr2 & 7))) << 4));
                    #pragma unroll
                    for (int k = 0; k < 4; k++)
                        MMA16816(oacc[n], pf[k], vb[2 * k], vb[2 * k + 1]);
                }
            }
        }
    }

    // Epilogue: quad-reduce l partials, normalize, store fp16
    lst[0] += __shfl_xor_sync(0xffffffffu, lst[0], 1);
    lst[0] += __shfl_xor_sync(0xffffffffu, lst[0], 2);
    lst[1] += __shfl_xor_sync(0xffffffffu, lst[1], 1);
    lst[1] += __shfl_xor_sync(0xffffffffu, lst[1], 2);
    const float inv_lo = 1.0f / lst[0];
    const float inv_hi = 1.0f / lst[1];
    #pragma unroll
    for (int n = 0; n < 8; n++) {
        const int col = h * HDd + n * 8 + 2 * t;
        *(__half2*)&Y[((size_t)(b * Tsz) + row_lo) * Csz + col] =
            __floats2half2_rn(oacc[n][0] * inv_lo, oacc[n][1] * inv_lo);
        *(__half2*)&Y[((size_t)(b * Tsz) + row_hi) * Csz + col] =
            __floats2half2_rn(oacc[n][2] * inv_hi, oacc[n][3] * inv_hi);
    }
}

// ===========================================================================
extern "C" void kernel_launch(void* const* d_in, const int* in_sizes, int n_in,
                              void* d_out, int out_size) {
    (void)in_sizes; (void)n_in; (void)out_size;
    const float* x      = (const float*)d_in[0];
    const float* w_attn = (const float*)d_in[1];
    const float* b_attn = (const float*)d_in[2];
    const float* w_proj = (const float*)d_in[3];
    const float* b_proj = (const float*)d_in[4];
    float* out = (float*)d_out;

    __half *p_xh, *p_wah, *p_wph, *p_qh, *p_kh, *p_vh, *p_yh;
    cudaGetSymbolAddress((void**)&p_xh,  g_xh);
    cudaGetSymbolAddress((void**)&p_wah, g_wah);
    cudaGetSymbolAddress((void**)&p_wph, g_wph);
    cudaGetSymbolAddress((void**)&p_qh,  g_qh);
    cudaGetSymbolAddress((void**)&p_kh,  g_kh);
    cudaGetSymbolAddress((void**)&p_vh,  g_vh);
    cudaGetSymbolAddress((void**)&p_yh,  g_yh);

    const int M = Bsz * Tsz;  // 4096
    const int na4 = M * Csz / 4;
    const int nb4 = Csz * 3 * Csz / 4;
    const int nc4 = Csz * Csz / 4;

    // 0) fp32 -> fp16 converts (single launch)
    f2h3_kernel<<<(na4 + nb4 + nc4 + 255) / 256, 256>>>(
        x, p_xh, na4, w_attn, p_wah, nb4, w_proj, p_wph, nc4);

    // 1) QKV GEMM with fused bias + RoPE + split/transpose epilogue
    cudaFuncSetAttribute(hgemm128<1>,
                         cudaFuncAttributeMaxDynamicSharedMemorySize, HG_SMEM);
    hgemm128<1><<<dim3(3 * Csz / 128, M / 128), 256, HG_SMEM>>>(
        p_xh, p_wah, b_attn, nullptr, M, 3 * Csz, Csz);

    // 2) Flash attention (fp16 out; Q tile 64, 2 CTAs/SM)
    cudaFuncSetAttribute(flash_mma,
                         cudaFuncAttributeMaxDynamicSharedMemorySize, FL_SMEM);
    flash_mma<<<dim3(Tsz / 64, Hn, Bsz), 128, FL_SMEM>>>(p_qh, p_kh, p_vh, p_yh);

    // 3) out = y @ w_proj + b_proj   (fp32 out)
    cudaFuncSetAttribute(hgemm128<0>,
                         cudaFuncAttributeMaxDynamicSharedMemorySize, HG_SMEM);
    hgemm128<0><<<dim3(Csz / 128, M / 128), 256, HG_SMEM>>>(
        p_yh, p_wph, b_proj, out, M, Csz, Csz);
}

// round 16
// speedup vs baseline: 1.0921x; 1.0255x over previous
#include <cuda_runtime.h>
#include <cuda_fp16.h>
#include <math.h>
#include <stdint.h>

#define Bsz 2
#define Tsz 2048
#define Csz 1024
#define Hn  16
#define HDd 64

#define SCALE_L2E 0.1803368801111244f   // 0.125 * log2(e)

// Scratch (fp16 pipeline)
__device__ __half g_xh [Bsz * Tsz * Csz];
__device__ __half g_wah[Csz * 3 * Csz];
__device__ __half g_wph[Csz * Csz];
__device__ __half g_qh[Bsz * Hn * Tsz * HDd];   // pre-scaled by SCALE_L2E
__device__ __half g_kh[Bsz * Hn * Tsz * HDd];
__device__ __half g_vh[Bsz * Hn * Tsz * HDd];
__device__ __half g_yh[Bsz * Tsz * Csz];

// ===========================================================================
// Helpers
// ===========================================================================
__device__ __forceinline__ uint32_t smem_u32(const void* p) {
    uint32_t a;
    asm("{ .reg .u64 t; cvta.to.shared.u64 t, %1; cvt.u32.u64 %0, t; }"
        : "=r"(a) : "l"(p));
    return a;
}

#define LDSM4(r0, r1, r2, r3, ad)                                              \
    asm volatile("ldmatrix.sync.aligned.m8n8.x4.shared.b16 {%0,%1,%2,%3}, [%4];" \
                 : "=r"(r0), "=r"(r1), "=r"(r2), "=r"(r3) : "r"(ad))

#define LDSM4T(r0, r1, r2, r3, ad)                                             \
    asm volatile("ldmatrix.sync.aligned.m8n8.x4.trans.shared.b16 {%0,%1,%2,%3}, [%4];" \
                 : "=r"(r0), "=r"(r1), "=r"(r2), "=r"(r3) : "r"(ad))

#define MMA16816(d, a, b0, b1)                                                 \
    asm volatile("mma.sync.aligned.m16n8k16.row.col.f32.f16.f16.f32 "          \
                 "{%0,%1,%2,%3}, {%4,%5,%6,%7}, {%8,%9}, {%0,%1,%2,%3};"       \
                 : "+f"((d)[0]), "+f"((d)[1]), "+f"((d)[2]), "+f"((d)[3])      \
                 : "r"((a)[0]), "r"((a)[1]), "r"((a)[2]), "r"((a)[3]),         \
                   "r"(b0), "r"(b1))

#define CP_ASYNC16(dst, src)                                                   \
    asm volatile("cp.async.cg.shared.global [%0], [%1], 16;"                   \
                 :: "r"(dst), "l"(src))
#define CP_COMMIT() asm volatile("cp.async.commit_group;" ::: "memory")
#define CP_WAIT1()  asm volatile("cp.async.wait_group 1;" ::: "memory")
#define CP_WAIT0()  asm volatile("cp.async.wait_group 0;" ::: "memory")

__device__ __forceinline__ float ex2f(float x) {
    float y;
    asm("ex2.approx.f32 %0, %1;" : "=f"(y) : "f"(x));
    return y;
}
__device__ __forceinline__ uint32_t packh2(float hi, float lo) {
    uint32_t r;
    asm("cvt.rn.f16x2.f32 %0, %1, %2;" : "=r"(r) : "f"(hi), "f"(lo));
    return r;
}
__device__ __forceinline__ uint32_t hex2(uint32_t x) {
    uint32_t y;
    asm("ex2.approx.f16x2 %0, %1;" : "=r"(y) : "r"(x));
    return y;
}

// ===========================================================================
// fp32 -> fp16 convert: three arrays in one launch
// ===========================================================================
__global__ void f2h3_kernel(const float* __restrict__ a, __half* __restrict__ ah, int na4,
                            const float* __restrict__ b, __half* __restrict__ bh, int nb4,
                            const float* __restrict__ c, __half* __restrict__ ch, int nc4) {
    int i = blockIdx.x * blockDim.x + threadIdx.x;
    const float* src; __half* dst;
    if (i < na4) { src = a; dst = ah; }
    else if (i < na4 + nb4) { i -= na4; src = b; dst = bh; }
    else { i -= na4 + nb4; if (i >= nc4) return; src = c; dst = ch; }
    float4 v = ((const float4*)src)[i];
    ((__half2*)dst)[2 * i]     = __floats2half2_rn(v.x, v.y);
    ((__half2*)dst)[2 * i + 1] = __floats2half2_rn(v.z, v.w);
}

// ===========================================================================
// HGEMM: 128x128 tile, BK=32, 8 warps (2M x 4N), warp tile 64x32, m16n8k16.
// 3-stage cp.async pipeline, ONE barrier per iteration.
// MODE 0: C = A@B + bias, fp32 out (proj).
// MODE 1: fused QKV epilogue — bias + RoPE + head-split/transpose, fp16 out.
// ===========================================================================
#define GSTAGE 24576
#define HG_SMEM (3 * GSTAGE)

template <int MODE>
__global__ __launch_bounds__(256, 2)
void hgemm128(const __half* __restrict__ A, const __half* __restrict__ B,
              const float* __restrict__ bias, float* __restrict__ Cv,
              int M, int N, int K) {
    extern __shared__ char sm[];
    const uint32_t sbase = smem_u32(sm);

    const int tid  = threadIdx.x;
    const int lane = tid & 31;
    const int wid  = tid >> 5;
    const int wm = wid >> 2;
    const int wn = wid & 3;
    const int m0 = blockIdx.y * 128;
    const int n0 = blockIdx.x * 128;
    const int NK = K >> 5;

    float acc[4][4][4] = {};

    auto issue = [&](int stg, int k0) {
        const uint32_t sA = sbase + stg * GSTAGE;
        const uint32_t sB = sA + 16384;
        #pragma unroll
        for (int i = 0; i < 2; i++) {
            const int idx = tid + i * 256;
            const int ra = idx >> 2, ca = idx & 3;
            CP_ASYNC16(sA + ra * 128 + ((ca ^ (ra & 7)) << 4),
                       A + (size_t)(m0 + ra) * K + k0 + ca * 8);
            const int rb = idx >> 4, cb = idx & 15;
            CP_ASYNC16(sB + rb * 256 + ((cb ^ (rb & 7)) << 4),
                       B + (size_t)(k0 + rb) * N + n0 + cb * 8);
        }
        CP_COMMIT();
    };

    issue(0, 0);
    issue(1, 32);

    for (int it = 0; it < NK; it++) {
        if (it == NK - 1) { CP_WAIT0(); } else { CP_WAIT1(); }
        __syncthreads();
        if (it + 2 < NK) issue((it + 2) % 3, (it + 2) * 32);

        const int stg = it % 3;
        const uint32_t aB = sbase + stg * GSTAGE;
        const uint32_t bB = aB + 16384;

        uint32_t vb[4][4];
        #pragma unroll
        for (int j = 0; j < 4; j++) {
            const int cn = wn * 4 + j;
            LDSM4T(vb[j][0], vb[j][1], vb[j][2], vb[j][3],
                   bB + lane * 256 + ((cn ^ (lane & 7)) << 4));
        }
        #pragma unroll
        for (int ks = 0; ks < 2; ks++) {
            uint32_t af[4][4];
            #pragma unroll
            for (int mt = 0; mt < 4; mt++) {
                const int row = wm * 64 + mt * 16 + (lane & 7) + ((lane >> 3) & 1) * 8;
                const int ch  = ks * 2 + (lane >> 4);
                LDSM4(af[mt][0], af[mt][1], af[mt][2], af[mt][3],
                      aB + row * 128 + ((ch ^ (row & 7)) << 4));
            }
            #pragma unroll
            for (int mt = 0; mt < 4; mt++)
                #pragma unroll
                for (int j = 0; j < 4; j++)
                    MMA16816(acc[mt][j], af[mt], vb[j][2 * ks], vb[j][2 * ks + 1]);
        }
    }

    if (MODE == 0) {
        #pragma unroll
        for (int mt = 0; mt < 4; mt++) {
            const int row_lo = m0 + wm * 64 + mt * 16 + (lane >> 2);
            const int row_hi = row_lo + 8;
            #pragma unroll
            for (int j = 0; j < 4; j++) {
                const int col = n0 + wn * 32 + j * 8 + (lane & 3) * 2;
                const float b0v = bias[col], b1v = bias[col + 1];
                float2 o0 = {acc[mt][j][0] + b0v, acc[mt][j][1] + b1v};
                float2 o1 = {acc[mt][j][2] + b0v, acc[mt][j][3] + b1v};
                *(float2*)&Cv[(size_t)row_lo * N + col] = o0;
                *(float2*)&Cv[(size_t)row_hi * N + col] = o1;
            }
        }
    } else {
        float* Cs = (float*)sm;   // 128 x 132 floats
        __syncthreads();
        #pragma unroll
        for (int mt = 0; mt < 4; mt++) {
            const int rl = wm * 64 + mt * 16 + (lane >> 2);
            #pragma unroll
            for (int j = 0; j < 4; j++) {
                const int cl = wn * 32 + j * 8 + (lane & 3) * 2;
                const float b0v = bias[n0 + cl], b1v = bias[n0 + cl + 1];
                Cs[rl * 132 + cl]           = acc[mt][j][0] + b0v;
                Cs[rl * 132 + cl + 1]       = acc[mt][j][1] + b1v;
                Cs[(rl + 8) * 132 + cl]     = acc[mt][j][2] + b0v;
                Cs[(rl + 8) * 132 + cl + 1] = acc[mt][j][3] + b1v;
            }
        }
        __syncthreads();

        const int region = n0 >> 10;
        const int hbase  = (n0 & 1023) >> 6;
        #pragma unroll 4
        for (int i = 0; i < 16; i++) {
            const int p  = tid + (i << 8);
            const int r  = p >> 5;
            const int d2 = p & 31;
            const int mrow = m0 + r;
            const int tpos = mrow & (Tsz - 1);
            const int bidx = mrow >> 11;
            float sn = 0.0f, cs = 0.0f;
            if (region < 2) {
                const float inv_ts =
                    exp2f(-(float)d2 * (13.287712379549449f / 32.0f));
                sincosf((float)tpos * inv_ts, &sn, &cs);
            }
            #pragma unroll
            for (int hh = 0; hh < 2; hh++) {
                const float first  = Cs[r * 132 + hh * 64 + d2];
                const float second = Cs[r * 132 + hh * 64 + d2 + 32];
                const size_t o =
                    ((size_t)(bidx * Hn + hbase + hh) * Tsz + tpos) * 64 + d2;
                if (region == 0) {
                    g_qh[o]      = __float2half_rn((first * cs - second * sn) * SCALE_L2E);
                    g_qh[o + 32] = __float2half_rn((second * cs + first * sn) * SCALE_L2E);
                } else if (region == 1) {
                    g_kh[o]      = __float2half_rn(first * cs - second * sn);
                    g_kh[o + 32] = __float2half_rn(second * cs + first * sn);
                } else {
                    g_vh[o]      = __float2half_rn(first);
                    g_vh[o + 32] = __float2half_rn(second);
                }
            }
        }
    }
}

// ===========================================================================
// Flash attention via mma.sync (fp16 in, fp32 accum), fp16 out.
// 128 threads / 4 warps; Q tile 64 (16 rows/warp), KV tile 128.
// 2-stage KV buffer (lookahead 1) -> smem 72KB -> 3 CTAs/SM; the extra
// co-resident CTA hides each CTA's serial softmax phase with HMMA work.
// Deferred l-sum (per-thread partials, quad-reduced in the epilogue).
// ===========================================================================
#define FL_SMEM 73728

__global__ __launch_bounds__(128, 3)
void flash_mma(const __half* __restrict__ Q,
               const __half* __restrict__ K,
               const __half* __restrict__ V,
               __half* __restrict__ Y) {
    extern __shared__ char smem[];
    char* Qs = smem;                      // 8 KB
    char* Kbase = smem + 8192;            // 2 x 16 KB
    char* Vbase = smem + 40960;           // 2 x 16 KB

    const int tid  = threadIdx.x;
    const int wid  = tid >> 5;
    const int lane = tid & 31;
    const int g = lane >> 2;
    const int t = lane & 3;

    const int qt = gridDim.x - 1 - blockIdx.x;    // long blocks first
    const int h  = blockIdx.y;
    const int b  = blockIdx.z;
    const size_t bh = (size_t)(b * Hn + h) * Tsz;
    const int qbase = qt * 64 + wid * 16;
    const int row_lo = qbase + g;
    const int row_hi = row_lo + 8;
    const int nkt = (qt >> 1) + 1;

    auto fl_issue = [&](int tile) {
        const uint32_t kB = smem_u32(Kbase + (tile & 1) * 16384);
        const uint32_t vB = smem_u32(Vbase + (tile & 1) * 16384);
        const size_t base = bh + (size_t)tile * 128;
        #pragma unroll
        for (int i = 0; i < 8; i++) {
            const int idx = tid + i * 128;
            const int r = idx >> 3;
            const int c = idx & 7;
            const uint32_t so = r * 128 + ((c ^ (r & 7)) << 4);
            CP_ASYNC16(kB + so, &K[(base + r) * HDd + c * 8]);
            CP_ASYNC16(vB + so, &V[(base + r) * HDd + c * 8]);
        }
        CP_COMMIT();
    };

    // Q tile: swizzled copy
    #pragma unroll
    for (int i = 0; i < 4; i++) {
        const int idx = tid + i * 128;
        const int r = idx >> 3;
        const int c = idx & 7;
        uint4 q = *(const uint4*)&Q[(bh + qt * 64 + r) * HDd + c * 8];
        *(uint4*)(Qs + r * 128 + ((c ^ (r & 7)) << 4)) = q;
    }
    fl_issue(0);
    __syncthreads();   // Q stores visible

    // Q fragments (persistent)
    uint32_t qf[4][4];
    {
        const uint32_t sQ = smem_u32(Qs);
        const int mat = lane >> 3;
        const int qr  = wid * 16 + (lane & 7) + ((mat & 1) << 3);
        #pragma unroll
        for (int k = 0; k < 4; k++) {
            const int chunk = 2 * k + (mat >> 1);
            LDSM4(qf[k][0], qf[k][1], qf[k][2], qf[k][3],
                  sQ + qr * 128 + (((chunk ^ (qr & 7))) << 4));
        }
    }

    float oacc[8][4] = {};
    float mst[2] = {-1e30f, -1e30f};
    float lst[2] = {0.0f, 0.0f};   // per-thread partials; reduced at the end

    for (int kt = 0; kt < nkt; kt++) {
        CP_WAIT0();        // tile kt landed
        __syncthreads();   // visibility + buffer (kt+1)&1 free (read in kt-1)
        if (kt + 1 < nkt) fl_issue(kt + 1);

        char* Kc = Kbase + (kt & 1) * 16384;
        char* Vc = Vbase + (kt & 1) * 16384;

        // GEMM1
        float sacc[16][4] = {};
        {
            const uint32_t sK = smem_u32(Kc);
            const int kr = lane & 7;
            const int c0 = lane >> 3;
            #pragma unroll
            for (int n = 0; n < 16; n++) {
                const int row = n * 8 + kr;
                uint32_t kb[8];
                const uint32_t rb = sK + row * 128;
                LDSM4(kb[0], kb[1], kb[2], kb[3],
                      rb + (((c0 ^ (row & 7))) << 4));
                LDSM4(kb[4], kb[5], kb[6], kb[7],
                      rb + ((((c0 + 4) ^ (row & 7))) << 4));
                #pragma unroll
                for (int k = 0; k < 4; k++)
                    MMA16816(sacc[n], qf[k], kb[2 * k], kb[2 * k + 1]);
            }
        }

        // Softmax (max quad-reduced; l kept as per-thread partial)
        const bool dotest = (kt == nkt - 1);
        float rmx_lo = -1e30f, rmx_hi = -1e30f;
        #pragma unroll
        for (int n = 0; n < 16; n++) {
            if (dotest) {
                const int cb = kt * 128 + n * 8 + 2 * t;
                if (cb     > row_lo) sacc[n][0] = -1e30f;
                if (cb + 1 > row_lo) sacc[n][1] = -1e30f;
                if (cb     > row_hi) sacc[n][2] = -1e30f;
                if (cb + 1 > row_hi) sacc[n][3] = -1e30f;
            }
            rmx_lo = fmaxf(rmx_lo, fmaxf(sacc[n][0], sacc[n][1]));
            rmx_hi = fmaxf(rmx_hi, fmaxf(sacc[n][2], sacc[n][3]));
        }
        rmx_lo = fmaxf(rmx_lo, __shfl_xor_sync(0xffffffffu, rmx_lo, 1));
        rmx_lo = fmaxf(rmx_lo, __shfl_xor_sync(0xffffffffu, rmx_lo, 2));
        rmx_hi = fmaxf(rmx_hi, __shfl_xor_sync(0xffffffffu, rmx_hi, 1));
        rmx_hi = fmaxf(rmx_hi, __shfl_xor_sync(0xffffffffu, rmx_hi, 2));

        const float mn_lo = fmaxf(mst[0], rmx_lo);
        const float mn_hi = fmaxf(mst[1], rmx_hi);
        const float corr_lo = ex2f(mst[0] - mn_lo);
        const float corr_hi = ex2f(mst[1] - mn_hi);
        mst[0] = mn_lo; mst[1] = mn_hi;

        uint32_t ph_lo[16], ph_hi[16];
        float sum_lo = 0.0f, sum_hi = 0.0f;
        #pragma unroll
        for (int n = 0; n < 16; n++) {
            ph_lo[n] = hex2(packh2(sacc[n][1] - mn_lo, sacc[n][0] - mn_lo));
            ph_hi[n] = hex2(packh2(sacc[n][3] - mn_hi, sacc[n][2] - mn_hi));
            const float2 flo = __half22float2(*(__half2*)&ph_lo[n]);
            const float2 fhi = __half22float2(*(__half2*)&ph_hi[n]);
            sum_lo += flo.x + flo.y;
            sum_hi += fhi.x + fhi.y;
        }
        lst[0] = lst[0] * corr_lo + sum_lo;
        lst[1] = lst[1] * corr_hi + sum_hi;

        #pragma unroll
        for (int n = 0; n < 8; n++) {
            oacc[n][0] *= corr_lo; oacc[n][1] *= corr_lo;
            oacc[n][2] *= corr_hi; oacc[n][3] *= corr_hi;
        }

        // GEMM2
        {
            const uint32_t sV = smem_u32(Vc);
            #pragma unroll
            for (int kh = 0; kh < 2; kh++) {
                uint32_t pf[4][4];
                #pragma unroll
                for (int k = 0; k < 4; k++) {
                    const int s0 = 8 * kh + 2 * k;
                    pf[k][0] = ph_lo[s0];
                    pf[k][1] = ph_hi[s0];
                    pf[k][2] = ph_lo[s0 + 1];
                    pf[k][3] = ph_hi[s0 + 1];
                }
                const int vr  = kh * 64 + (lane >> 3) * 8 + (lane & 7);
                const int vr2 = vr + 32;
                #pragma unroll
                for (int n = 0; n < 8; n++) {
                    uint32_t vb[8];
                    LDSM4T(vb[0], vb[1], vb[2], vb[3],
                           sV + vr * 128 + (((n ^ (vr & 7))) << 4));
                    LDSM4T(vb[4], vb[5], vb[6], vb[7],
                           sV + vr2 * 128 + (((n ^ (vr2 & 7))) << 4));
                    #pragma unroll
                    for (int k = 0; k < 4; k++)
                        MMA16816(oacc[n], pf[k], vb[2 * k], vb[2 * k + 1]);
                }
            }
        }
    }

    // Epilogue: quad-reduce l partials, normalize, store fp16
    lst[0] += __shfl_xor_sync(0xffffffffu, lst[0], 1);
    lst[0] += __shfl_xor_sync(0xffffffffu, lst[0], 2);
    lst[1] += __shfl_xor_sync(0xffffffffu, lst[1], 1);
    lst[1] += __shfl_xor_sync(0xffffffffu, lst[1], 2);
    const float inv_lo = 1.0f / lst[0];
    const float inv_hi = 1.0f / lst[1];
    #pragma unroll
    for (int n = 0; n < 8; n++) {
        const int col = h * HDd + n * 8 + 2 * t;
        *(__half2*)&Y[((size_t)(b * Tsz) + row_lo) * Csz + col] =
            __floats2half2_rn(oacc[n][0] * inv_lo, oacc[n][1] * inv_lo);
        *(__half2*)&Y[((size_t)(b * Tsz) + row_hi) * Csz + col] =
            __floats2half2_rn(oacc[n][2] * inv_hi, oacc[n][3] * inv_hi);
    }
}

// ===========================================================================
extern "C" void kernel_launch(void* const* d_in, const int* in_sizes, int n_in,
                              void* d_out, int out_size) {
    (void)in_sizes; (void)n_in; (void)out_size;
    const float* x      = (const float*)d_in[0];
    const float* w_attn = (const float*)d_in[1];
    const float* b_attn = (const float*)d_in[2];
    const float* w_proj = (const float*)d_in[3];
    const float* b_proj = (const float*)d_in[4];
    float* out = (float*)d_out;

    __half *p_xh, *p_wah, *p_wph, *p_qh, *p_kh, *p_vh, *p_yh;
    cudaGetSymbolAddress((void**)&p_xh,  g_xh);
    cudaGetSymbolAddress((void**)&p_wah, g_wah);
    cudaGetSymbolAddress((void**)&p_wph, g_wph);
    cudaGetSymbolAddress((void**)&p_qh,  g_qh);
    cudaGetSymbolAddress((void**)&p_kh,  g_kh);
    cudaGetSymbolAddress((void**)&p_vh,  g_vh);
    cudaGetSymbolAddress((void**)&p_yh,  g_yh);

    const int M = Bsz * Tsz;  // 4096
    const int na4 = M * Csz / 4;
    const int nb4 = Csz * 3 * Csz / 4;
    const int nc4 = Csz * Csz / 4;

    // 0) fp32 -> fp16 converts (single launch)
    f2h3_kernel<<<(na4 + nb4 + nc4 + 255) / 256, 256>>>(
        x, p_xh, na4, w_attn, p_wah, nb4, w_proj, p_wph, nc4);

    // 1) QKV GEMM with fused bias + RoPE + split/transpose epilogue
    cudaFuncSetAttribute(hgemm128<1>,
                         cudaFuncAttributeMaxDynamicSharedMemorySize, HG_SMEM);
    hgemm128<1><<<dim3(3 * Csz / 128, M / 128), 256, HG_SMEM>>>(
        p_xh, p_wah, b_attn, nullptr, M, 3 * Csz, Csz);

    // 2) Flash attention (fp16 out; Q tile 64, 3 CTAs/SM)
    cudaFuncSetAttribute(flash_mma,
                         cudaFuncAttributeMaxDynamicSharedMemorySize, FL_SMEM);
    flash_mma<<<dim3(Tsz / 64, Hn, Bsz), 128, FL_SMEM>>>(p_qh, p_kh, p_vh, p_yh);

    // 3) out = y @ w_proj + b_proj   (fp32 out)
    cudaFuncSetAttribute(hgemm128<0>,
                         cudaFuncAttributeMaxDynamicSharedMemorySize, HG_SMEM);
    hgemm128<0><<<dim3(Csz / 128, M / 128), 256, HG_SMEM>>>(
        p_yh, p_wph, b_proj, out, M, Csz, Csz);
}

// round 17
// speedup vs baseline: 1.1132x; 1.0193x over previous
#include <cuda_runtime.h>
#include <cuda_fp16.h>
#include <math.h>
#include <stdint.h>

#define Bsz 2
#define Tsz 2048
#define Csz 1024
#define Hn  16
#define HDd 64

#define SCALE_L2E 0.1803368801111244f   // 0.125 * log2(e)

// Scratch (fp16 pipeline)
__device__ __half g_xh [Bsz * Tsz * Csz];
__device__ __half g_wah[Csz * 3 * Csz];
__device__ __half g_wph[Csz * Csz];
__device__ __half g_qh[Bsz * Hn * Tsz * HDd];   // pre-scaled by SCALE_L2E
__device__ __half g_kh[Bsz * Hn * Tsz * HDd];
__device__ __half g_vh[Bsz * Hn * Tsz * HDd];
__device__ __half g_yh[Bsz * Tsz * Csz];

// ===========================================================================
// Helpers
// ===========================================================================
__device__ __forceinline__ uint32_t smem_u32(const void* p) {
    uint32_t a;
    asm("{ .reg .u64 t; cvta.to.shared.u64 t, %1; cvt.u32.u64 %0, t; }"
        : "=r"(a) : "l"(p));
    return a;
}

#define LDSM4(r0, r1, r2, r3, ad)                                              \
    asm volatile("ldmatrix.sync.aligned.m8n8.x4.shared.b16 {%0,%1,%2,%3}, [%4];" \
                 : "=r"(r0), "=r"(r1), "=r"(r2), "=r"(r3) : "r"(ad))

#define LDSM4T(r0, r1, r2, r3, ad)                                             \
    asm volatile("ldmatrix.sync.aligned.m8n8.x4.trans.shared.b16 {%0,%1,%2,%3}, [%4];" \
                 : "=r"(r0), "=r"(r1), "=r"(r2), "=r"(r3) : "r"(ad))

#define MMA16816(d, a, b0, b1)                                                 \
    asm volatile("mma.sync.aligned.m16n8k16.row.col.f32.f16.f16.f32 "          \
                 "{%0,%1,%2,%3}, {%4,%5,%6,%7}, {%8,%9}, {%0,%1,%2,%3};"       \
                 : "+f"((d)[0]), "+f"((d)[1]), "+f"((d)[2]), "+f"((d)[3])      \
                 : "r"((a)[0]), "r"((a)[1]), "r"((a)[2]), "r"((a)[3]),         \
                   "r"(b0), "r"(b1))

#define CP_ASYNC16(dst, src)                                                   \
    asm volatile("cp.async.cg.shared.global [%0], [%1], 16;"                   \
                 :: "r"(dst), "l"(src))
#define CP_COMMIT() asm volatile("cp.async.commit_group;" ::: "memory")
#define CP_WAIT1()  asm volatile("cp.async.wait_group 1;" ::: "memory")
#define CP_WAIT0()  asm volatile("cp.async.wait_group 0;" ::: "memory")

__device__ __forceinline__ float ex2f(float x) {
    float y;
    asm("ex2.approx.f32 %0, %1;" : "=f"(y) : "f"(x));
    return y;
}
__device__ __forceinline__ uint32_t packh2(float hi, float lo) {
    uint32_t r;
    asm("cvt.rn.f16x2.f32 %0, %1, %2;" : "=r"(r) : "f"(hi), "f"(lo));
    return r;
}
__device__ __forceinline__ uint32_t hex2(uint32_t x) {
    uint32_t y;
    asm("ex2.approx.f16x2 %0, %1;" : "=r"(y) : "r"(x));
    return y;
}

// ===========================================================================
// fp32 -> fp16 convert: three arrays in one launch
// ===========================================================================
__global__ void f2h3_kernel(const float* __restrict__ a, __half* __restrict__ ah, int na4,
                            const float* __restrict__ b, __half* __restrict__ bh, int nb4,
                            const float* __restrict__ c, __half* __restrict__ ch, int nc4) {
    int i = blockIdx.x * blockDim.x + threadIdx.x;
    const float* src; __half* dst;
    if (i < na4) { src = a; dst = ah; }
    else if (i < na4 + nb4) { i -= na4; src = b; dst = bh; }
    else { i -= na4 + nb4; if (i >= nc4) return; src = c; dst = ch; }
    float4 v = ((const float4*)src)[i];
    ((__half2*)dst)[2 * i]     = __floats2half2_rn(v.x, v.y);
    ((__half2*)dst)[2 * i + 1] = __floats2half2_rn(v.z, v.w);
}

// ===========================================================================
// HGEMM: 128x128 tile, BK=32, 8 warps (2M x 4N), warp tile 64x32, m16n8k16.
// 3-stage cp.async pipeline, ONE barrier per iteration.
// MODE 0: C = A@B + bias, fp32 out (proj).
// MODE 1: fused QKV epilogue — bias + RoPE + head-split/transpose, fp16 out.
// ===========================================================================
#define GSTAGE 24576
#define HG_SMEM (3 * GSTAGE)

template <int MODE>
__global__ __launch_bounds__(256, 2)
void hgemm128(const __half* __restrict__ A, const __half* __restrict__ B,
              const float* __restrict__ bias, float* __restrict__ Cv,
              int M, int N, int K) {
    extern __shared__ char sm[];
    const uint32_t sbase = smem_u32(sm);

    const int tid  = threadIdx.x;
    const int lane = tid & 31;
    const int wid  = tid >> 5;
    const int wm = wid >> 2;
    const int wn = wid & 3;
    const int m0 = blockIdx.y * 128;
    const int n0 = blockIdx.x * 128;
    const int NK = K >> 5;

    float acc[4][4][4] = {};

    auto issue = [&](int stg, int k0) {
        const uint32_t sA = sbase + stg * GSTAGE;
        const uint32_t sB = sA + 16384;
        #pragma unroll
        for (int i = 0; i < 2; i++) {
            const int idx = tid + i * 256;
            const int ra = idx >> 2, ca = idx & 3;
            CP_ASYNC16(sA + ra * 128 + ((ca ^ (ra & 7)) << 4),
                       A + (size_t)(m0 + ra) * K + k0 + ca * 8);
            const int rb = idx >> 4, cb = idx & 15;
            CP_ASYNC16(sB + rb * 256 + ((cb ^ (rb & 7)) << 4),
                       B + (size_t)(k0 + rb) * N + n0 + cb * 8);
        }
        CP_COMMIT();
    };

    issue(0, 0);
    issue(1, 32);

    for (int it = 0; it < NK; it++) {
        if (it == NK - 1) { CP_WAIT0(); } else { CP_WAIT1(); }
        __syncthreads();
        if (it + 2 < NK) issue((it + 2) % 3, (it + 2) * 32);

        const int stg = it % 3;
        const uint32_t aB = sbase + stg * GSTAGE;
        const uint32_t bB = aB + 16384;

        uint32_t vb[4][4];
        #pragma unroll
        for (int j = 0; j < 4; j++) {
            const int cn = wn * 4 + j;
            LDSM4T(vb[j][0], vb[j][1], vb[j][2], vb[j][3],
                   bB + lane * 256 + ((cn ^ (lane & 7)) << 4));
        }
        #pragma unroll
        for (int ks = 0; ks < 2; ks++) {
            uint32_t af[4][4];
            #pragma unroll
            for (int mt = 0; mt < 4; mt++) {
                const int row = wm * 64 + mt * 16 + (lane & 7) + ((lane >> 3) & 1) * 8;
                const int ch  = ks * 2 + (lane >> 4);
                LDSM4(af[mt][0], af[mt][1], af[mt][2], af[mt][3],
                      aB + row * 128 + ((ch ^ (row & 7)) << 4));
            }
            #pragma unroll
            for (int mt = 0; mt < 4; mt++)
                #pragma unroll
                for (int j = 0; j < 4; j++)
                    MMA16816(acc[mt][j], af[mt], vb[j][2 * ks], vb[j][2 * ks + 1]);
        }
    }

    if (MODE == 0) {
        #pragma unroll
        for (int mt = 0; mt < 4; mt++) {
            const int row_lo = m0 + wm * 64 + mt * 16 + (lane >> 2);
            const int row_hi = row_lo + 8;
            #pragma unroll
            for (int j = 0; j < 4; j++) {
                const int col = n0 + wn * 32 + j * 8 + (lane & 3) * 2;
                const float b0v = bias[col], b1v = bias[col + 1];
                float2 o0 = {acc[mt][j][0] + b0v, acc[mt][j][1] + b1v};
                float2 o1 = {acc[mt][j][2] + b0v, acc[mt][j][3] + b1v};
                *(float2*)&Cv[(size_t)row_lo * N + col] = o0;
                *(float2*)&Cv[(size_t)row_hi * N + col] = o1;
            }
        }
    } else {
        float* Cs = (float*)sm;   // 128 x 132 floats
        __syncthreads();
        #pragma unroll
        for (int mt = 0; mt < 4; mt++) {
            const int rl = wm * 64 + mt * 16 + (lane >> 2);
            #pragma unroll
            for (int j = 0; j < 4; j++) {
                const int cl = wn * 32 + j * 8 + (lane & 3) * 2;
                const float b0v = bias[n0 + cl], b1v = bias[n0 + cl + 1];
                Cs[rl * 132 + cl]           = acc[mt][j][0] + b0v;
                Cs[rl * 132 + cl + 1]       = acc[mt][j][1] + b1v;
                Cs[(rl + 8) * 132 + cl]     = acc[mt][j][2] + b0v;
                Cs[(rl + 8) * 132 + cl + 1] = acc[mt][j][3] + b1v;
            }
        }
        __syncthreads();

        const int region = n0 >> 10;
        const int hbase  = (n0 & 1023) >> 6;
        #pragma unroll 4
        for (int i = 0; i < 16; i++) {
            const int p  = tid + (i << 8);
            const int r  = p >> 5;
            const int d2 = p & 31;
            const int mrow = m0 + r;
            const int tpos = mrow & (Tsz - 1);
            const int bidx = mrow >> 11;
            float sn = 0.0f, cs = 0.0f;
            if (region < 2) {
                const float inv_ts =
                    exp2f(-(float)d2 * (13.287712379549449f / 32.0f));
                sincosf((float)tpos * inv_ts, &sn, &cs);
            }
            #pragma unroll
            for (int hh = 0; hh < 2; hh++) {
                const float first  = Cs[r * 132 + hh * 64 + d2];
                const float second = Cs[r * 132 + hh * 64 + d2 + 32];
                const size_t o =
                    ((size_t)(bidx * Hn + hbase + hh) * Tsz + tpos) * 64 + d2;
                if (region == 0) {
                    g_qh[o]      = __float2half_rn((first * cs - second * sn) * SCALE_L2E);
                    g_qh[o + 32] = __float2half_rn((second * cs + first * sn) * SCALE_L2E);
                } else if (region == 1) {
                    g_kh[o]      = __float2half_rn(first * cs - second * sn);
                    g_kh[o + 32] = __float2half_rn(second * cs + first * sn);
                } else {
                    g_vh[o]      = __float2half_rn(first);
                    g_vh[o + 32] = __float2half_rn(second);
                }
            }
        }
    }
}

// ===========================================================================
// Flash attention per-tile body, templated on number of n8-column tiles (NT)
// and the first n-tile that needs causal mask tests (MASK_FROM).
//   main tiles:          <16, 16>  (full width, no masking)
//   last tile, qt even:  <8,  0>   (only first 64 columns valid)
//   last tile, qt odd:   <16, 8>   (first 64 columns below diagonal)
// ===========================================================================
template <int NT, int MASK_FROM>
__device__ __forceinline__ void flash_tile(
    const uint32_t (&qf)[4][4], float (&oacc)[8][4],
    float (&mst)[2], float (&lst)[2],
    uint32_t sK, uint32_t sV,
    int kt, int row_lo, int row_hi, int t, int lane) {

    // GEMM1: S[16 x NT*8] per warp
    float sacc[NT][4];
    {
        const int kr = lane & 7;
        const int c0 = lane >> 3;
        #pragma unroll
        for (int n = 0; n < NT; n++) {
            sacc[n][0] = sacc[n][1] = sacc[n][2] = sacc[n][3] = 0.0f;
            const int row = n * 8 + kr;
            uint32_t kb[8];
            const uint32_t rb = sK + row * 128;
            LDSM4(kb[0], kb[1], kb[2], kb[3],
                  rb + (((c0 ^ (row & 7))) << 4));
            LDSM4(kb[4], kb[5], kb[6], kb[7],
                  rb + ((((c0 + 4) ^ (row & 7))) << 4));
            #pragma unroll
            for (int k = 0; k < 4; k++)
                MMA16816(sacc[n], qf[k], kb[2 * k], kb[2 * k + 1]);
        }
    }

    // Mask (only n >= MASK_FROM can cross the diagonal) + row max
    float rmx_lo = -1e30f, rmx_hi = -1e30f;
    #pragma unroll
    for (int n = 0; n < NT; n++) {
        if (n >= MASK_FROM) {
            const int cb = kt * 128 + n * 8 + 2 * t;
            if (cb     > row_lo) sacc[n][0] = -1e30f;
            if (cb + 1 > row_lo) sacc[n][1] = -1e30f;
            if (cb     > row_hi) sacc[n][2] = -1e30f;
            if (cb + 1 > row_hi) sacc[n][3] = -1e30f;
        }
        rmx_lo = fmaxf(rmx_lo, fmaxf(sacc[n][0], sacc[n][1]));
        rmx_hi = fmaxf(rmx_hi, fmaxf(sacc[n][2], sacc[n][3]));
    }
    rmx_lo = fmaxf(rmx_lo, __shfl_xor_sync(0xffffffffu, rmx_lo, 1));
    rmx_lo = fmaxf(rmx_lo, __shfl_xor_sync(0xffffffffu, rmx_lo, 2));
    rmx_hi = fmaxf(rmx_hi, __shfl_xor_sync(0xffffffffu, rmx_hi, 1));
    rmx_hi = fmaxf(rmx_hi, __shfl_xor_sync(0xffffffffu, rmx_hi, 2));

    const float mn_lo = fmaxf(mst[0], rmx_lo);
    const float mn_hi = fmaxf(mst[1], rmx_hi);
    const float corr_lo = ex2f(mst[0] - mn_lo);
    const float corr_hi = ex2f(mst[1] - mn_hi);
    mst[0] = mn_lo; mst[1] = mn_hi;

    uint32_t ph_lo[NT], ph_hi[NT];
    float sum_lo = 0.0f, sum_hi = 0.0f;
    #pragma unroll
    for (int n = 0; n < NT; n++) {
        ph_lo[n] = hex2(packh2(sacc[n][1] - mn_lo, sacc[n][0] - mn_lo));
        ph_hi[n] = hex2(packh2(sacc[n][3] - mn_hi, sacc[n][2] - mn_hi));
        const float2 flo = __half22float2(*(__half2*)&ph_lo[n]);
        const float2 fhi = __half22float2(*(__half2*)&ph_hi[n]);
        sum_lo += flo.x + flo.y;
        sum_hi += fhi.x + fhi.y;
    }
    lst[0] = lst[0] * corr_lo + sum_lo;   // per-thread partial (deferred reduce)
    lst[1] = lst[1] * corr_hi + sum_hi;

    #pragma unroll
    for (int n = 0; n < 8; n++) {
        oacc[n][0] *= corr_lo; oacc[n][1] *= corr_lo;
        oacc[n][2] *= corr_hi; oacc[n][3] *= corr_hi;
    }

    // GEMM2: O += P @ V over NT/8 k64 halves
    #pragma unroll
    for (int kh = 0; kh < NT / 8; kh++) {
        uint32_t pf[4][4];
        #pragma unroll
        for (int k = 0; k < 4; k++) {
            const int s0 = 8 * kh + 2 * k;
            pf[k][0] = ph_lo[s0];
            pf[k][1] = ph_hi[s0];
            pf[k][2] = ph_lo[s0 + 1];
            pf[k][3] = ph_hi[s0 + 1];
        }
        const int vr  = kh * 64 + (lane >> 3) * 8 + (lane & 7);
        const int vr2 = vr + 32;
        #pragma unroll
        for (int n = 0; n < 8; n++) {
            uint32_t vb[8];
            LDSM4T(vb[0], vb[1], vb[2], vb[3],
                   sV + vr * 128 + (((n ^ (vr & 7))) << 4));
            LDSM4T(vb[4], vb[5], vb[6], vb[7],
                   sV + vr2 * 128 + (((n ^ (vr2 & 7))) << 4));
            #pragma unroll
            for (int k = 0; k < 4; k++)
                MMA16816(oacc[n], pf[k], vb[2 * k], vb[2 * k + 1]);
        }
    }
}

// ===========================================================================
// Flash attention via mma.sync (fp16 in, fp32 accum), fp16 out.
// 128 threads / 4 warps; Q tile 64 (16 rows/warp), KV tile 128.
// 2-stage KV buffer -> smem 72KB -> 3 CTAs/SM (cross-CTA softmax/MMA overlap).
// Diagonal tile specialized: even qt computes only the valid 64 columns.
// ===========================================================================
#define FL_SMEM 73728

__global__ __launch_bounds__(128, 3)
void flash_mma(const __half* __restrict__ Q,
               const __half* __restrict__ K,
               const __half* __restrict__ V,
               __half* __restrict__ Y) {
    extern __shared__ char smem[];
    char* Qs = smem;                      // 8 KB
    char* Kbase = smem + 8192;            // 2 x 16 KB
    char* Vbase = smem + 40960;           // 2 x 16 KB

    const int tid  = threadIdx.x;
    const int wid  = tid >> 5;
    const int lane = tid & 31;
    const int g = lane >> 2;
    const int t = lane & 3;

    const int qt = gridDim.x - 1 - blockIdx.x;    // long blocks first
    const int h  = blockIdx.y;
    const int b  = blockIdx.z;
    const size_t bh = (size_t)(b * Hn + h) * Tsz;
    const int qbase = qt * 64 + wid * 16;
    const int row_lo = qbase + g;
    const int row_hi = row_lo + 8;
    const int nkt = (qt >> 1) + 1;

    auto fl_issue = [&](int tile) {
        const uint32_t kB = smem_u32(Kbase + (tile & 1) * 16384);
        const uint32_t vB = smem_u32(Vbase + (tile & 1) * 16384);
        const size_t base = bh + (size_t)tile * 128;
        #pragma unroll
        for (int i = 0; i < 8; i++) {
            const int idx = tid + i * 128;
            const int r = idx >> 3;
            const int c = idx & 7;
            const uint32_t so = r * 128 + ((c ^ (r & 7)) << 4);
            CP_ASYNC16(kB + so, &K[(base + r) * HDd + c * 8]);
            CP_ASYNC16(vB + so, &V[(base + r) * HDd + c * 8]);
        }
        CP_COMMIT();
    };

    // Q tile: swizzled copy
    #pragma unroll
    for (int i = 0; i < 4; i++) {
        const int idx = tid + i * 128;
        const int r = idx >> 3;
        const int c = idx & 7;
        uint4 q = *(const uint4*)&Q[(bh + qt * 64 + r) * HDd + c * 8];
        *(uint4*)(Qs + r * 128 + ((c ^ (r & 7)) << 4)) = q;
    }
    fl_issue(0);
    __syncthreads();   // Q stores visible

    // Q fragments (persistent)
    uint32_t qf[4][4];
    {
        const uint32_t sQ = smem_u32(Qs);
        const int mat = lane >> 3;
        const int qr  = wid * 16 + (lane & 7) + ((mat & 1) << 3);
        #pragma unroll
        for (int k = 0; k < 4; k++) {
            const int chunk = 2 * k + (mat >> 1);
            LDSM4(qf[k][0], qf[k][1], qf[k][2], qf[k][3],
                  sQ + qr * 128 + (((chunk ^ (qr & 7))) << 4));
        }
    }

    float oacc[8][4] = {};
    float mst[2] = {-1e30f, -1e30f};
    float lst[2] = {0.0f, 0.0f};

    for (int kt = 0; kt < nkt; kt++) {
        CP_WAIT0();        // tile kt landed
        __syncthreads();   // visibility + buffer (kt+1)&1 free
        if (kt + 1 < nkt) fl_issue(kt + 1);

        const uint32_t sK = smem_u32(Kbase + (kt & 1) * 16384);
        const uint32_t sV = smem_u32(Vbase + (kt & 1) * 16384);

        if (kt < nkt - 1) {
            flash_tile<16, 16>(qf, oacc, mst, lst, sK, sV,
                               kt, row_lo, row_hi, t, lane);
        } else if (qt & 1) {
            flash_tile<16, 8>(qf, oacc, mst, lst, sK, sV,
                              kt, row_lo, row_hi, t, lane);
        } else {
            flash_tile<8, 0>(qf, oacc, mst, lst, sK, sV,
                             kt, row_lo, row_hi, t, lane);
        }
    }

    // Epilogue: quad-reduce l partials, normalize, store fp16
    lst[0] += __shfl_xor_sync(0xffffffffu, lst[0], 1);
    lst[0] += __shfl_xor_sync(0xffffffffu, lst[0], 2);
    lst[1] += __shfl_xor_sync(0xffffffffu, lst[1], 1);
    lst[1] += __shfl_xor_sync(0xffffffffu, lst[1], 2);
    const float inv_lo = 1.0f / lst[0];
    const float inv_hi = 1.0f / lst[1];
    #pragma unroll
    for (int n = 0; n < 8; n++) {
        const int col = h * HDd + n * 8 + 2 * t;
        *(__half2*)&Y[((size_t)(b * Tsz) + row_lo) * Csz + col] =
            __floats2half2_rn(oacc[n][0] * inv_lo, oacc[n][1] * inv_lo);
        *(__half2*)&Y[((size_t)(b * Tsz) + row_hi) * Csz + col] =
            __floats2half2_rn(oacc[n][2] * inv_hi, oacc[n][3] * inv_hi);
    }
}

// ===========================================================================
extern "C" void kernel_launch(void* const* d_in, const int* in_sizes, int n_in,
                              void* d_out, int out_size) {
    (void)in_sizes; (void)n_in; (void)out_size;
    const float* x      = (const float*)d_in[0];
    const float* w_attn = (const float*)d_in[1];
    const float* b_attn = (const float*)d_in[2];
    const float* w_proj = (const float*)d_in[3];
    const float* b_proj = (const float*)d_in[4];
    float* out = (float*)d_out;

    __half *p_xh, *p_wah, *p_wph, *p_qh, *p_kh, *p_vh, *p_yh;
    cudaGetSymbolAddress((void**)&p_xh,  g_xh);
    cudaGetSymbolAddress((void**)&p_wah, g_wah);
    cudaGetSymbolAddress((void**)&p_wph, g_wph);
    cudaGetSymbolAddress((void**)&p_qh,  g_qh);
    cudaGetSymbolAddress((void**)&p_kh,  g_kh);
    cudaGetSymbolAddress((void**)&p_vh,  g_vh);
    cudaGetSymbolAddress((void**)&p_yh,  g_yh);

    const int M = Bsz * Tsz;  // 4096
    const int na4 = M * Csz / 4;
    const int nb4 = Csz * 3 * Csz / 4;
    const int nc4 = Csz * Csz / 4;

    // 0) fp32 -> fp16 converts (single launch)
    f2h3_kernel<<<(na4 + nb4 + nc4 + 255) / 256, 256>>>(
        x, p_xh, na4, w_attn, p_wah, nb4, w_proj, p_wph, nc4);

    // 1) QKV GEMM with fused bias + RoPE + split/transpose epilogue
    cudaFuncSetAttribute(hgemm128<1>,
                         cudaFuncAttributeMaxDynamicSharedMemorySize, HG_SMEM);
    hgemm128<1><<<dim3(3 * Csz / 128, M / 128), 256, HG_SMEM>>>(
        p_xh, p_wah, b_attn, nullptr, M, 3 * Csz, Csz);

    // 2) Flash attention (fp16 out; Q tile 64, 3 CTAs/SM, diag specialization)
    cudaFuncSetAttribute(flash_mma,
                         cudaFuncAttributeMaxDynamicSharedMemorySize, FL_SMEM);
    flash_mma<<<dim3(Tsz / 64, Hn, Bsz), 128, FL_SMEM>>>(p_qh, p_kh, p_vh, p_yh);

    // 3) out = y @ w_proj + b_proj   (fp32 out)
    cudaFuncSetAttribute(hgemm128<0>,
                         cudaFuncAttributeMaxDynamicSharedMemorySize, HG_SMEM);
    hgemm128<0><<<dim3(Csz / 128, M / 128), 256, HG_SMEM>>>(
        p_yh, p_wph, b_proj, out, M, Csz, Csz);
}